// round 8
// baseline (speedup 1.0000x reference)
#include <cuda_runtime.h>
#include <cuda_bf16.h>
#include <cstdint>

// 3x3 cross-correlation, 4096x4096 fp32, pad=1, stride=1.
// out[i][j] = sum_{dr,dc} w[dr*3+dc] * x[i+dr-1][j+dc-1] + bias
//
// Rolling-accumulator + distance-2 prefetch + PACKED f32x2 math (FFMA2):
//  - warp strip = 128 wide x 16 rows; lane owns 4 consecutive cols.
//  - all FMA/ADD done on packed f32 pairs via PTX fma.rn.f32x2/add.rn.f32x2
//    (ptxas never auto-generates these) -> ~halves math instruction count.
//  - per input row (4 outputs): 1 LDG.128 + 2 edge LDGs + 2 SHFL + 5 packs +
//    18 FFMA2 + 6 ADD2 + 1 STG.128.

#define N_IMG 4096
#define TW    128
#define RPT   16
#define WARPS 8
#define TILE_H (RPT * WARPS)   // 128 rows per CTA
#define FULLMASK 0xFFFFFFFFu

typedef unsigned long long u64;

#define PACK2(d, lo, hi) \
    asm("mov.b64 %0, {%1, %2};" : "=l"(d) : "f"(lo), "f"(hi))
#define UNPACK2(lo, hi, s) \
    asm("mov.b64 {%0, %1}, %2;" : "=f"(lo), "=f"(hi) : "l"(s))
#define FMA2(d, a, b, c) \
    asm("fma.rn.f32x2 %0, %1, %2, %3;" : "=l"(d) : "l"(a), "l"(b), "l"(c))
#define MUL2(d, a, b) \
    asm("mul.rn.f32x2 %0, %1, %2;" : "=l"(d) : "l"(a), "l"(b))
#define ADD2(d, a, b) \
    asm("add.rn.f32x2 %0, %1, %2;" : "=l"(d) : "l"(a), "l"(b))

struct Raw { float4 v; float e; };

__device__ __forceinline__ Raw fetch_fast(const float* __restrict__ x,
                                          int grow, int c0, int lane)
{
    const float* rowp = x + (size_t)grow * N_IMG;
    Raw r;
    r.v = *reinterpret_cast<const float4*>(rowp + c0);
    r.e = 0.f;
    if (lane == 0)  r.e = rowp[c0 - 1];
    if (lane == 31) r.e = rowp[c0 + 4];
    return r;
}

__device__ __forceinline__ Raw fetch_guard(const float* __restrict__ x,
                                           int grow, int c0, int lane)
{
    Raw r;
    r.v = make_float4(0.f, 0.f, 0.f, 0.f);
    r.e = 0.f;
    if ((unsigned)grow < (unsigned)N_IMG) {   // warp-uniform
        const float* rowp = x + (size_t)grow * N_IMG;
        r.v = *reinterpret_cast<const float4*>(rowp + c0);
        if (lane == 0 && c0 > 0)          r.e = rowp[c0 - 1];
        if (lane == 31 && c0 + 4 < N_IMG) r.e = rowp[c0 + 4];
    }
    return r;
}

template<bool GUARD>
__device__ __forceinline__ void do_strip(const float* __restrict__ x,
                                         float* __restrict__ out,
                                         int row0, int tile_x, int lane,
                                         const u64* ww, u64 bb)
{
    const int c0 = tile_x + lane * 4;

    u64 zero; PACK2(zero, 0.f, 0.f);
    u64 accP01 = zero, accP23 = zero;   // out row (i-1)
    u64 accQ01 = zero, accQ23 = zero;   // out row i

    Raw pfA, pfB;
    if (GUARD) {
        pfA = fetch_guard(x, row0 - 1, c0, lane);
        pfB = fetch_guard(x, row0,     c0, lane);
    } else {
        pfA = fetch_fast(x, row0 - 1, c0, lane);
        pfB = fetch_fast(x, row0,     c0, lane);
    }

    #pragma unroll
    for (int i = -1; i <= RPT; i++) {
        // expand input row (row0+i): v0..v5 = cols c0-1 .. c0+4
        float lf = __shfl_up_sync(FULLMASK, pfA.v.w, 1);
        float rt = __shfl_down_sync(FULLMASK, pfA.v.x, 1);
        if (lane == 0)  lf = pfA.e;
        if (lane == 31) rt = pfA.e;
        const float v0 = lf,      v1 = pfA.v.x, v2 = pfA.v.y;
        const float v3 = pfA.v.z, v4 = pfA.v.w, v5 = rt;
        pfA = pfB;

        // prefetch row (row0+i+2)
        if (i + 2 <= RPT) {
            if (GUARD) pfB = fetch_guard(x, row0 + i + 2, c0, lane);
            else       pfB = fetch_fast (x, row0 + i + 2, c0, lane);
        }

        // packed shifted windows
        u64 p01, p12, p23, p34, p45;
        PACK2(p01, v0, v1);
        PACK2(p12, v1, v2);
        PACK2(p23, v2, v3);
        PACK2(p34, v3, v4);
        PACK2(p45, v4, v5);

        // weight-row horizontal 3-taps, packed (2 outputs per FFMA2 chain)
        u64 h0a, h0b, h1a, h1b, h2a, h2b, t;

        MUL2(t, ww[2], p23); FMA2(t, ww[1], p12, t); FMA2(h0a, ww[0], p01, t);
        MUL2(t, ww[2], p45); FMA2(t, ww[1], p34, t); FMA2(h0b, ww[0], p23, t);

        MUL2(t, ww[5], p23); FMA2(t, ww[4], p12, t); FMA2(h1a, ww[3], p01, t);
        MUL2(t, ww[5], p45); FMA2(t, ww[4], p34, t); FMA2(h1b, ww[3], p23, t);

        MUL2(t, ww[8], p23); FMA2(t, ww[7], p12, t); FMA2(h2a, ww[6], p01, t);
        MUL2(t, ww[8], p45); FMA2(t, ww[7], p34, t); FMA2(h2b, ww[6], p23, t);

        // input row g: h2 -> out g-1 (accP), h1 -> out g (accQ), h0 -> out g+1
        ADD2(accP01, accP01, h2a);
        ADD2(accP23, accP23, h2b);
        ADD2(accQ01, accQ01, h1a);
        ADD2(accQ23, accQ23, h1b);

        if (i >= 1) {   // accP = completed output row row0+i-1
            u64 s01, s23;
            ADD2(s01, accP01, bb);
            ADD2(s23, accP23, bb);
            float4 o;
            UNPACK2(o.x, o.y, s01);
            UNPACK2(o.z, o.w, s23);
            *reinterpret_cast<float4*>(
                out + (size_t)(row0 + i - 1) * N_IMG + c0) = o;
        }

        accP01 = accQ01; accP23 = accQ23;
        accQ01 = h0a;    accQ23 = h0b;
    }
}

__global__ __launch_bounds__(256, 4)
void conv3x3_pack_kernel(const float* __restrict__ x,
                         const float* __restrict__ w9,
                         const float* __restrict__ bias,
                         float* __restrict__ out)
{
    const int lane   = threadIdx.x & 31;
    const int warp   = threadIdx.x >> 5;
    const int tile_x = blockIdx.x * TW;
    const int row0   = blockIdx.y * TILE_H + warp * RPT;

    u64 ww[9];
    #pragma unroll
    for (int i = 0; i < 9; i++) {
        const float wi = __ldg(&w9[i]);
        PACK2(ww[i], wi, wi);
    }
    const float b = __ldg(&bias[0]);
    u64 bb; PACK2(bb, b, b);

    const bool guard = (row0 == 0) | (row0 + RPT >= N_IMG) |
                       (tile_x == 0) | (tile_x + TW >= N_IMG);

    if (!guard)
        do_strip<false>(x, out, row0, tile_x, lane, ww, bb);
    else
        do_strip<true >(x, out, row0, tile_x, lane, ww, bb);
}

extern "C" void kernel_launch(void* const* d_in, const int* in_sizes, int n_in,
                              void* d_out, int out_size)
{
    const float* x    = (const float*)d_in[0];   // 4096*4096
    const float* w9   = (const float*)d_in[1];   // 9
    const float* bias = (const float*)d_in[2];   // 1
    float* out        = (float*)d_out;           // 4096*4096

    dim3 block(256, 1, 1);
    dim3 grid(N_IMG / TW, N_IMG / TILE_H, 1);    // 32 x 32 = 1024 CTAs
    conv3x3_pack_kernel<<<grid, block>>>(x, w9, bias, out);
}

// round 9
// speedup vs baseline: 1.1691x; 1.1691x over previous
#include <cuda_runtime.h>
#include <cuda_bf16.h>
#include <cstdint>

// 3x3 cross-correlation, 4096x4096 fp32, pad=1, stride=1.
// out[i][j] = sum_{dr,dc} w[dr*3+dc] * x[i+dr-1][j+dc-1] + bias
//
// Direct-form register pipeline, single-wave residency:
//  - CTA = 128 threads = 4 warps, each warp owns a 256-wide x 16-row strip
//    (stacked vertically). Grid 16x64 = 1024 CTAs; 7 CTAs/SM -> ALL CTAs
//    resident in one wave (no wave-quantization tail).
//  - lane owns 8 cols; 3 expanded rows (10 floats) in regs; 9 FMA/output.
//  - distance-2 raw prefetch (pfA,pfB); fetch gated so exactly RPT+2 rows
//    are read per strip (1.125x read amplification).

#define N_IMG 4096
#define TW    256
#define RPT   16
#define WARPS 4
#define TILE_H (RPT * WARPS)   // 64 rows per CTA
#define FULLMASK 0xFFFFFFFFu

struct Raw { float4 lo, hi; float e; };

__device__ __forceinline__ Raw fetch_fast(const float* __restrict__ x,
                                          int grow, int c0, int lane)
{
    const float* rowp = x + (size_t)grow * N_IMG;
    Raw r;
    r.lo = *reinterpret_cast<const float4*>(rowp + c0);
    r.hi = *reinterpret_cast<const float4*>(rowp + c0 + 4);
    r.e  = 0.f;
    if (lane == 0)  r.e = rowp[c0 - 1];
    if (lane == 31) r.e = rowp[c0 + 8];
    return r;
}

__device__ __forceinline__ Raw fetch_guard(const float* __restrict__ x,
                                           int grow, int c0, int lane)
{
    Raw r;
    r.lo = make_float4(0.f,0.f,0.f,0.f);
    r.hi = make_float4(0.f,0.f,0.f,0.f);
    r.e  = 0.f;
    if ((unsigned)grow < (unsigned)N_IMG) {   // warp-uniform
        const float* rowp = x + (size_t)grow * N_IMG;
        r.lo = *reinterpret_cast<const float4*>(rowp + c0);
        r.hi = *reinterpret_cast<const float4*>(rowp + c0 + 4);
        if (lane == 0 && c0 > 0)          r.e = rowp[c0 - 1];
        if (lane == 31 && c0 + 8 < N_IMG) r.e = rowp[c0 + 8];
    }
    return r;
}

// raw -> 10-float shifted row (cols c0-1 .. c0+8)
__device__ __forceinline__ void expand(const Raw& q, int lane, float* v)
{
    float lf = __shfl_up_sync(FULLMASK, q.hi.w, 1);
    float rt = __shfl_down_sync(FULLMASK, q.lo.x, 1);
    if (lane == 0)  lf = q.e;
    if (lane == 31) rt = q.e;
    v[0]=lf;     v[1]=q.lo.x; v[2]=q.lo.y; v[3]=q.lo.z; v[4]=q.lo.w;
    v[5]=q.hi.x; v[6]=q.hi.y; v[7]=q.hi.z; v[8]=q.hi.w; v[9]=rt;
}

template<bool GUARD>
__device__ __forceinline__ void do_strip(const float* __restrict__ x,
                                         float* __restrict__ out,
                                         int row0, int tile_x, int lane,
                                         const float* w, float b)
{
    const int c0 = tile_x + lane * 8;
    float r[3][10];
    Raw pfA, pfB;

    if (GUARD) {
        Raw a = fetch_guard(x, row0 - 1, c0, lane);
        Raw q = fetch_guard(x, row0,     c0, lane);
        pfA   = fetch_guard(x, row0 + 1, c0, lane);
        pfB   = fetch_guard(x, row0 + 2, c0, lane);
        expand(a, lane, r[0]);
        expand(q, lane, r[1]);
    } else {
        Raw a = fetch_fast(x, row0 - 1, c0, lane);
        Raw q = fetch_fast(x, row0,     c0, lane);
        pfA   = fetch_fast(x, row0 + 1, c0, lane);
        pfB   = fetch_fast(x, row0 + 2, c0, lane);
        expand(a, lane, r[0]);
        expand(q, lane, r[1]);
    }

    #pragma unroll
    for (int i = 0; i < RPT; i++) {
        // row (row0+i+1) becomes resident
        expand(pfA, lane, r[(i + 2) % 3]);
        pfA = pfB;

        // fetch row (row0+i+3), consumed at iter i+2; needed only while
        // row0+i+3 <= row0+RPT  ->  i <= RPT-3  (exactly RPT+2 rows total)
        if (i <= RPT - 3) {
            if (GUARD) pfB = fetch_guard(x, row0 + i + 3, c0, lane);
            else       pfB = fetch_fast (x, row0 + i + 3, c0, lane);
        }

        const float* r0 = r[ i      % 3];
        const float* r1 = r[(i + 1) % 3];
        const float* r2 = r[(i + 2) % 3];

        float o[8];
        #pragma unroll
        for (int j = 0; j < 8; j++) {
            float acc = b;
            acc = fmaf(w[0], r0[j    ], acc);
            acc = fmaf(w[1], r0[j + 1], acc);
            acc = fmaf(w[2], r0[j + 2], acc);
            acc = fmaf(w[3], r1[j    ], acc);
            acc = fmaf(w[4], r1[j + 1], acc);
            acc = fmaf(w[5], r1[j + 2], acc);
            acc = fmaf(w[6], r2[j    ], acc);
            acc = fmaf(w[7], r2[j + 1], acc);
            acc = fmaf(w[8], r2[j + 2], acc);
            o[j] = acc;
        }

        float* orow = out + (size_t)(row0 + i) * N_IMG + c0;
        *reinterpret_cast<float4*>(orow)     = make_float4(o[0], o[1], o[2], o[3]);
        *reinterpret_cast<float4*>(orow + 4) = make_float4(o[4], o[5], o[6], o[7]);
    }
}

__global__ __launch_bounds__(128, 7)
void conv3x3_wave1_kernel(const float* __restrict__ x,
                          const float* __restrict__ w9,
                          const float* __restrict__ bias,
                          float* __restrict__ out)
{
    const int lane   = threadIdx.x & 31;
    const int warp   = threadIdx.x >> 5;
    const int tile_x = blockIdx.x * TW;
    const int row0   = blockIdx.y * TILE_H + warp * RPT;

    float w[9];
    #pragma unroll
    for (int i = 0; i < 9; i++) w[i] = __ldg(&w9[i]);
    const float b = __ldg(&bias[0]);

    const bool guard = (row0 == 0) | (row0 + RPT >= N_IMG) |
                       (tile_x == 0) | (tile_x + TW >= N_IMG);

    if (!guard)
        do_strip<false>(x, out, row0, tile_x, lane, w, b);
    else
        do_strip<true >(x, out, row0, tile_x, lane, w, b);
}

extern "C" void kernel_launch(void* const* d_in, const int* in_sizes, int n_in,
                              void* d_out, int out_size)
{
    const float* x    = (const float*)d_in[0];   // 4096*4096
    const float* w9   = (const float*)d_in[1];   // 9
    const float* bias = (const float*)d_in[2];   // 1
    float* out        = (float*)d_out;           // 4096*4096

    dim3 block(128, 1, 1);
    dim3 grid(N_IMG / TW, N_IMG / TILE_H, 1);    // 16 x 64 = 1024 CTAs
    conv3x3_wave1_kernel<<<grid, block>>>(x, w9, bias, out);
}

// round 10
// speedup vs baseline: 1.2452x; 1.0651x over previous
#include <cuda_runtime.h>
#include <cuda_bf16.h>
#include <cstdint>

// 3x3 cross-correlation, 4096x4096 fp32, pad=1, stride=1.
// out[i][j] = sum_{dr,dc} w[dr*3+dc] * x[i+dr-1][j+dc-1] + bias
//
// Direct-form register pipeline (R9) + streaming stores:
//  - CTA = 128 threads = 4 warps, each warp owns a 256-wide x 16-row strip.
//    Grid 16x64 = 1024 CTAs, 7 CTAs/SM -> single-wave residency.
//  - lane owns 8 cols; 3 expanded rows (10 floats) in regs; 9 FMA/output.
//  - distance-2 raw prefetch; exactly RPT+2 input rows read per strip.
//  - stores use __stcs (evict-first): the 64MB write stream no longer
//    evicts halo rows from L2, so vertical-halo re-reads stay L2 hits.

#define N_IMG 4096
#define TW    256
#define RPT   16
#define WARPS 4
#define TILE_H (RPT * WARPS)   // 64 rows per CTA
#define FULLMASK 0xFFFFFFFFu

struct Raw { float4 lo, hi; float e; };

__device__ __forceinline__ Raw fetch_fast(const float* __restrict__ x,
                                          int grow, int c0, int lane)
{
    const float* rowp = x + (size_t)grow * N_IMG;
    Raw r;
    r.lo = *reinterpret_cast<const float4*>(rowp + c0);
    r.hi = *reinterpret_cast<const float4*>(rowp + c0 + 4);
    r.e  = 0.f;
    if (lane == 0)  r.e = rowp[c0 - 1];
    if (lane == 31) r.e = rowp[c0 + 8];
    return r;
}

__device__ __forceinline__ Raw fetch_guard(const float* __restrict__ x,
                                           int grow, int c0, int lane)
{
    Raw r;
    r.lo = make_float4(0.f,0.f,0.f,0.f);
    r.hi = make_float4(0.f,0.f,0.f,0.f);
    r.e  = 0.f;
    if ((unsigned)grow < (unsigned)N_IMG) {   // warp-uniform
        const float* rowp = x + (size_t)grow * N_IMG;
        r.lo = *reinterpret_cast<const float4*>(rowp + c0);
        r.hi = *reinterpret_cast<const float4*>(rowp + c0 + 4);
        if (lane == 0 && c0 > 0)          r.e = rowp[c0 - 1];
        if (lane == 31 && c0 + 8 < N_IMG) r.e = rowp[c0 + 8];
    }
    return r;
}

// raw -> 10-float shifted row (cols c0-1 .. c0+8)
__device__ __forceinline__ void expand(const Raw& q, int lane, float* v)
{
    float lf = __shfl_up_sync(FULLMASK, q.hi.w, 1);
    float rt = __shfl_down_sync(FULLMASK, q.lo.x, 1);
    if (lane == 0)  lf = q.e;
    if (lane == 31) rt = q.e;
    v[0]=lf;     v[1]=q.lo.x; v[2]=q.lo.y; v[3]=q.lo.z; v[4]=q.lo.w;
    v[5]=q.hi.x; v[6]=q.hi.y; v[7]=q.hi.z; v[8]=q.hi.w; v[9]=rt;
}

template<bool GUARD>
__device__ __forceinline__ void do_strip(const float* __restrict__ x,
                                         float* __restrict__ out,
                                         int row0, int tile_x, int lane,
                                         const float* w, float b)
{
    const int c0 = tile_x + lane * 8;
    float r[3][10];
    Raw pfA, pfB;

    if (GUARD) {
        Raw a = fetch_guard(x, row0 - 1, c0, lane);
        Raw q = fetch_guard(x, row0,     c0, lane);
        pfA   = fetch_guard(x, row0 + 1, c0, lane);
        pfB   = fetch_guard(x, row0 + 2, c0, lane);
        expand(a, lane, r[0]);
        expand(q, lane, r[1]);
    } else {
        Raw a = fetch_fast(x, row0 - 1, c0, lane);
        Raw q = fetch_fast(x, row0,     c0, lane);
        pfA   = fetch_fast(x, row0 + 1, c0, lane);
        pfB   = fetch_fast(x, row0 + 2, c0, lane);
        expand(a, lane, r[0]);
        expand(q, lane, r[1]);
    }

    #pragma unroll
    for (int i = 0; i < RPT; i++) {
        // row (row0+i+1) becomes resident
        expand(pfA, lane, r[(i + 2) % 3]);
        pfA = pfB;

        // fetch row (row0+i+3), consumed at iter i+2; gate so exactly
        // RPT+2 rows are read per strip
        if (i <= RPT - 3) {
            if (GUARD) pfB = fetch_guard(x, row0 + i + 3, c0, lane);
            else       pfB = fetch_fast (x, row0 + i + 3, c0, lane);
        }

        const float* r0 = r[ i      % 3];
        const float* r1 = r[(i + 1) % 3];
        const float* r2 = r[(i + 2) % 3];

        float o[8];
        #pragma unroll
        for (int j = 0; j < 8; j++) {
            float acc = b;
            acc = fmaf(w[0], r0[j    ], acc);
            acc = fmaf(w[1], r0[j + 1], acc);
            acc = fmaf(w[2], r0[j + 2], acc);
            acc = fmaf(w[3], r1[j    ], acc);
            acc = fmaf(w[4], r1[j + 1], acc);
            acc = fmaf(w[5], r1[j + 2], acc);
            acc = fmaf(w[6], r2[j    ], acc);
            acc = fmaf(w[7], r2[j + 1], acc);
            acc = fmaf(w[8], r2[j + 2], acc);
            o[j] = acc;
        }

        float* orow = out + (size_t)(row0 + i) * N_IMG + c0;
        __stcs(reinterpret_cast<float4*>(orow),
               make_float4(o[0], o[1], o[2], o[3]));
        __stcs(reinterpret_cast<float4*>(orow + 4),
               make_float4(o[4], o[5], o[6], o[7]));
    }
}

__global__ __launch_bounds__(128, 7)
void conv3x3_stream_kernel(const float* __restrict__ x,
                           const float* __restrict__ w9,
                           const float* __restrict__ bias,
                           float* __restrict__ out)
{
    const int lane   = threadIdx.x & 31;
    const int warp   = threadIdx.x >> 5;
    const int tile_x = blockIdx.x * TW;
    const int row0   = blockIdx.y * TILE_H + warp * RPT;

    float w[9];
    #pragma unroll
    for (int i = 0; i < 9; i++) w[i] = __ldg(&w9[i]);
    const float b = __ldg(&bias[0]);

    const bool guard = (row0 == 0) | (row0 + RPT >= N_IMG) |
                       (tile_x == 0) | (tile_x + TW >= N_IMG);

    if (!guard)
        do_strip<false>(x, out, row0, tile_x, lane, w, b);
    else
        do_strip<true >(x, out, row0, tile_x, lane, w, b);
}

extern "C" void kernel_launch(void* const* d_in, const int* in_sizes, int n_in,
                              void* d_out, int out_size)
{
    const float* x    = (const float*)d_in[0];   // 4096*4096
    const float* w9   = (const float*)d_in[1];   // 9
    const float* bias = (const float*)d_in[2];   // 1
    float* out        = (float*)d_out;           // 4096*4096

    dim3 block(128, 1, 1);
    dim3 grid(N_IMG / TW, N_IMG / TILE_H, 1);    // 16 x 64 = 1024 CTAs
    conv3x3_stream_kernel<<<grid, block>>>(x, w9, bias, out);
}